// round 14
// baseline (speedup 1.0000x reference)
#include <cuda_runtime.h>
#include <cuda_fp16.h>

#define N_NODES 100000
#define F0 256
#define F1 128
#define F2 64
#define MAX_E 1600000
#define NB 391   // ceil(N_NODES/256)
#define AP 136   // As row pitch (halves): frag banks (4*grp+thr)%32 distinct
#define BP 40    // Bs row pitch (halves): frag banks (20*c+thr)%32 distinct

// Scratch (allocation-free rule: __device__ globals). 16B-aligned for vector access.
__device__ int   g_is_i32 = 0;       // sticky: same input -> same value every call
__device__ int   g_deg[N_NODES];     // zero at load; re-zeroed by gather2 each call
__device__ float g_dinv[N_NODES];
__device__ int   g_row32[MAX_E];
__device__ int   g_col32[MAX_E];
__device__ int   g_csr[MAX_E];
__device__ int   g_pref[N_NODES];
__device__ int   g_bsum[NB];
__device__ int   g_boff[NB];
__device__ int   g_rowptr[N_NODES];
__device__ int   g_fill[N_NODES];
__device__ __align__(16) __half g_h1[N_NODES * F1];  // dinv-scaled x@W1 (fp16)
__device__ __align__(16) __half g_y1[N_NODES * F1];  // relu output (fp16)
__device__ __align__(16) __half g_h2[N_NODES * F2];  // dinv-scaled (y1@W2) (fp16)

// ---------------- fp16 mma helper ----------------

__device__ __forceinline__ void mma_f16(float* c, unsigned a0, unsigned a1,
                                        unsigned a2, unsigned a3,
                                        unsigned b0, unsigned b1) {
    asm volatile(
        "mma.sync.aligned.m16n8k16.row.col.f32.f16.f16.f32 "
        "{%0,%1,%2,%3}, {%4,%5,%6,%7}, {%8,%9}, {%0,%1,%2,%3};\n"
        : "+f"(c[0]), "+f"(c[1]), "+f"(c[2]), "+f"(c[3])
        : "r"(a0), "r"(a1), "r"(a2), "r"(a3), "r"(b0), "r"(b1));
}

// ---------------- dtype detection (1 block) ----------------

__global__ void k_detect(const long long* __restrict__ ei) {
    long long v = ei[threadIdx.x];
    if (v < 0 || v >= N_NODES) g_is_i32 = 1;   // sticky, deterministic
}

__global__ void k_prep_edges(const void* __restrict__ eiv, int E) {
    int e = blockIdx.x * blockDim.x + threadIdx.x;
    if (e >= E) return;
    int r, c;
    if (g_is_i32) {
        const int* p = (const int*)eiv;
        r = p[e]; c = p[E + e];
    } else {
        const long long* p = (const long long*)eiv;
        r = (int)p[e]; c = (int)p[E + e];
    }
    r = min(max(r, 0), N_NODES - 1);
    c = min(max(c, 0), N_NODES - 1);
    g_row32[e] = r;
    g_col32[e] = c;
    atomicAdd(&g_deg[c], 1);
}

// ---------------- CSR build (dinv fused into block scan) ----------------

__global__ void k_scan_block() {
    __shared__ int s[256];
    int tid = threadIdx.x;
    int i = blockIdx.x * 256 + tid;
    int v = (i < N_NODES) ? g_deg[i] : 0;
    if (i < N_NODES) g_dinv[i] = rsqrtf((float)(v + 1));
    s[tid] = v;
    __syncthreads();
#pragma unroll
    for (int d = 1; d < 256; d <<= 1) {
        int t = (tid >= d) ? s[tid - d] : 0;
        __syncthreads();
        s[tid] += t;
        __syncthreads();
    }
    if (i < N_NODES) g_pref[i] = s[tid] - v;
    if (tid == 255) g_bsum[blockIdx.x] = s[255];
}

__global__ void k_scan_top() {
    __shared__ int s[512];
    int tid = threadIdx.x;
    int v = (tid < NB) ? g_bsum[tid] : 0;
    s[tid] = v;
    __syncthreads();
#pragma unroll
    for (int d = 1; d < 512; d <<= 1) {
        int t = (tid >= d) ? s[tid - d] : 0;
        __syncthreads();
        s[tid] += t;
        __syncthreads();
    }
    if (tid < NB) g_boff[tid] = s[tid] - v;
}

__global__ void k_scan_add() {
    int i = blockIdx.x * blockDim.x + threadIdx.x;
    if (i < N_NODES) {
        int rp = g_pref[i] + g_boff[i >> 8];
        g_rowptr[i] = rp;
        g_fill[i] = rp;
    }
}

__global__ void k_fill(int E) {
    int e = blockIdx.x * blockDim.x + threadIdx.x;
    if (e >= E) return;
    int c = g_col32[e];
    int pos = atomicAdd(&g_fill[c], 1);
    g_csr[pos] = g_row32[e];
}

// ---------------- GEMM1 (fp16 mma): g_h1 = fp16( (x @ W1) * dinv[row] )
// Block 128x128, warps 4(m)x2(n), warp tile 32x64, K chunks of 32.

__global__ void __launch_bounds__(256) k_gemm1(const float* __restrict__ x,
                                               const float* __restrict__ W) {
    __shared__ __align__(16) __half As[128 * AP];
    __shared__ __align__(16) __half Bs[128 * BP];   // [n][k] for col-major B frags
    int tid = threadIdx.x;
    int lane = tid & 31;
    int wid = tid >> 5;
    int warp_m = wid & 3;
    int warp_n = wid >> 2;
    int grp = lane >> 2;
    int thr = lane & 3;
    int mbase = blockIdx.x * 128;

    float acc[2][8][4];
#pragma unroll
    for (int mf = 0; mf < 2; mf++)
#pragma unroll
        for (int nf = 0; nf < 8; nf++)
#pragma unroll
            for (int q = 0; q < 4; q++) acc[mf][nf][q] = 0.f;

    for (int kt = 0; kt < F0; kt += 32) {
        // A: 128 rows x 32 k = 2048 half2; 8 per thread (fp32 -> fp16)
#pragma unroll
        for (int i = 0; i < 8; i++) {
            int idx2 = tid + i * 256;
            int m = idx2 >> 4;              // 16 half2 per row
            int kk = (idx2 & 15) * 2;
            int gm = mbase + m;
            float2 v = make_float2(0.f, 0.f);
            if (gm < N_NODES) v = *(const float2*)(x + gm * F0 + kt + kk);
            *(half2*)(As + m * AP + kk) = __floats2half2_rn(v.x, v.y);
        }
        // B: W1 chunk [kt..kt+32) x 128n -> Bs[n][k] fp16 (transposed store)
        {
            int n = tid & 127;
            int kq = tid >> 7;              // 0..1 -> k-local base kq*16
#pragma unroll
            for (int kk2 = 0; kk2 < 16; kk2 += 2) {
                int k = kt + kq * 16 + kk2;
                float f0 = W[k * F1 + n];
                float f1 = W[(k + 1) * F1 + n];
                *(half2*)(Bs + n * BP + kq * 16 + kk2) = __floats2half2_rn(f0, f1);
            }
        }
        __syncthreads();

#pragma unroll
        for (int kk = 0; kk < 32; kk += 16) {
            unsigned a[2][4];
#pragma unroll
            for (int mf = 0; mf < 2; mf++) {
                int r = warp_m * 32 + mf * 16 + grp;
                a[mf][0] = *(const unsigned*)(As + r * AP + kk + 2 * thr);
                a[mf][1] = *(const unsigned*)(As + (r + 8) * AP + kk + 2 * thr);
                a[mf][2] = *(const unsigned*)(As + r * AP + kk + 8 + 2 * thr);
                a[mf][3] = *(const unsigned*)(As + (r + 8) * AP + kk + 8 + 2 * thr);
            }
#pragma unroll
            for (int nf = 0; nf < 8; nf++) {
                int cN = warp_n * 64 + nf * 8 + grp;
                unsigned b0 = *(const unsigned*)(Bs + cN * BP + kk + 2 * thr);
                unsigned b1 = *(const unsigned*)(Bs + cN * BP + kk + 8 + 2 * thr);
#pragma unroll
                for (int mf = 0; mf < 2; mf++)
                    mma_f16(acc[mf][nf], a[mf][0], a[mf][1], a[mf][2], a[mf][3], b0, b1);
            }
        }
        __syncthreads();
    }

#pragma unroll
    for (int mf = 0; mf < 2; mf++) {
        int r0 = mbase + warp_m * 32 + mf * 16 + grp;
        int r1 = r0 + 8;
        float s0 = (r0 < N_NODES) ? g_dinv[r0] : 0.f;
        float s1 = (r1 < N_NODES) ? g_dinv[r1] : 0.f;
#pragma unroll
        for (int nf = 0; nf < 8; nf++) {
            int cNo = warp_n * 64 + nf * 8 + thr * 2;
            if (r0 < N_NODES)
                *(half2*)(g_h1 + r0 * F1 + cNo) =
                    __floats2half2_rn(acc[mf][nf][0] * s0, acc[mf][nf][1] * s0);
            if (r1 < N_NODES)
                *(half2*)(g_h1 + r1 * F1 + cNo) =
                    __floats2half2_rn(acc[mf][nf][2] * s1, acc[mf][nf][3] * s1);
        }
    }
}

// ---------------- Gather layer 1: warp per node, 4-way unroll

__global__ void __launch_bounds__(256) k_gather1(const float* __restrict__ b1) {
    int w = (blockIdx.x * blockDim.x + threadIdx.x) >> 5;
    if (w >= N_NODES) return;
    int lane = threadIdx.x & 31;
    int c = w;
    int fo = lane * 4;

    float2 a0 = __half22float2(*(const half2*)(g_h1 + c * F1 + fo));
    float2 a1 = __half22float2(*(const half2*)(g_h1 + c * F1 + fo + 2));
    float4 acc = make_float4(a0.x, a0.y, a1.x, a1.y);   // self-loop term

    int start = g_rowptr[c];
    int end = start + g_deg[c];

    int j = start;
    for (; j + 4 <= end; j += 4) {
        int i0 = g_csr[j], i1 = g_csr[j + 1], i2 = g_csr[j + 2], i3 = g_csr[j + 3];
        uint2 u0 = *(const uint2*)(g_h1 + i0 * F1 + fo);
        uint2 u1 = *(const uint2*)(g_h1 + i1 * F1 + fo);
        uint2 u2 = *(const uint2*)(g_h1 + i2 * F1 + fo);
        uint2 u3 = *(const uint2*)(g_h1 + i3 * F1 + fo);
        float2 p;
        p = __half22float2(*(half2*)&u0.x); acc.x += p.x; acc.y += p.y;
        p = __half22float2(*(half2*)&u0.y); acc.z += p.x; acc.w += p.y;
        p = __half22float2(*(half2*)&u1.x); acc.x += p.x; acc.y += p.y;
        p = __half22float2(*(half2*)&u1.y); acc.z += p.x; acc.w += p.y;
        p = __half22float2(*(half2*)&u2.x); acc.x += p.x; acc.y += p.y;
        p = __half22float2(*(half2*)&u2.y); acc.z += p.x; acc.w += p.y;
        p = __half22float2(*(half2*)&u3.x); acc.x += p.x; acc.y += p.y;
        p = __half22float2(*(half2*)&u3.y); acc.z += p.x; acc.w += p.y;
    }
    for (; j < end; j++) {
        int i0 = g_csr[j];
        uint2 u0 = *(const uint2*)(g_h1 + i0 * F1 + fo);
        float2 p;
        p = __half22float2(*(half2*)&u0.x); acc.x += p.x; acc.y += p.y;
        p = __half22float2(*(half2*)&u0.y); acc.z += p.x; acc.w += p.y;
    }

    float s = g_dinv[c];
    float4 bb = *(const float4*)(b1 + fo);
    acc.x = fmaxf(fmaf(s, acc.x, bb.x), 0.f);
    acc.y = fmaxf(fmaf(s, acc.y, bb.y), 0.f);
    acc.z = fmaxf(fmaf(s, acc.z, bb.z), 0.f);
    acc.w = fmaxf(fmaf(s, acc.w, bb.w), 0.f);
    *(half2*)(g_y1 + c * F1 + fo)     = __floats2half2_rn(acc.x, acc.y);
    *(half2*)(g_y1 + c * F1 + fo + 2) = __floats2half2_rn(acc.z, acc.w);
}

// ---------------- GEMM2 (fp16 mma): g_h2 = fp16( (y1 @ W2) * dinv[row] )
// Block 128x64, 8 warps of 16 rows, K chunks of 32. A bytes copied (no cvt).

__global__ void __launch_bounds__(256) k_gemm2(const float* __restrict__ W) {
    __shared__ __align__(16) __half As[128 * AP];
    __shared__ __align__(16) __half Bs[64 * BP];
    int tid = threadIdx.x;
    int lane = tid & 31;
    int wid = tid >> 5;
    int grp = lane >> 2;
    int thr = lane & 3;
    int mbase = blockIdx.x * 128;

    float acc[8][4];
#pragma unroll
    for (int nf = 0; nf < 8; nf++)
#pragma unroll
        for (int q = 0; q < 4; q++) acc[nf][q] = 0.f;

    for (int kt = 0; kt < F1; kt += 32) {
        // A: straight fp16 copy from g_y1 (1024 uint2; 4 per thread)
#pragma unroll
        for (int i = 0; i < 4; i++) {
            int idx4 = tid + i * 256;
            int m = idx4 >> 3;              // 8 uint2 per row
            int kk = (idx4 & 7) * 4;
            int gm = mbase + m;
            uint2 u = make_uint2(0u, 0u);
            if (gm < N_NODES) u = *(const uint2*)(g_y1 + gm * F1 + kt + kk);
            *(uint2*)(As + m * AP + kk) = u;
        }
        // B: W2 chunk [kt..kt+32) x 64n -> Bs[n][k] fp16
        {
            int n = tid & 63;
            int kq = tid >> 6;              // 0..3 -> k-local base kq*8
#pragma unroll
            for (int kk2 = 0; kk2 < 8; kk2 += 2) {
                int k = kt + kq * 8 + kk2;
                float f0 = W[k * F2 + n];
                float f1 = W[(k + 1) * F2 + n];
                *(half2*)(Bs + n * BP + kq * 8 + kk2) = __floats2half2_rn(f0, f1);
            }
        }
        __syncthreads();

        int r = wid * 16 + grp;
#pragma unroll
        for (int kk = 0; kk < 32; kk += 16) {
            unsigned a0 = *(const unsigned*)(As + r * AP + kk + 2 * thr);
            unsigned a1 = *(const unsigned*)(As + (r + 8) * AP + kk + 2 * thr);
            unsigned a2 = *(const unsigned*)(As + r * AP + kk + 8 + 2 * thr);
            unsigned a3 = *(const unsigned*)(As + (r + 8) * AP + kk + 8 + 2 * thr);
#pragma unroll
            for (int nf = 0; nf < 8; nf++) {
                int cN = nf * 8 + grp;
                unsigned b0 = *(const unsigned*)(Bs + cN * BP + kk + 2 * thr);
                unsigned b1 = *(const unsigned*)(Bs + cN * BP + kk + 8 + 2 * thr);
                mma_f16(acc[nf], a0, a1, a2, a3, b0, b1);
            }
        }
        __syncthreads();
    }

    int r0 = mbase + wid * 16 + grp;
    int r1 = r0 + 8;
    float s0 = (r0 < N_NODES) ? g_dinv[r0] : 0.f;
    float s1 = (r1 < N_NODES) ? g_dinv[r1] : 0.f;
#pragma unroll
    for (int nf = 0; nf < 8; nf++) {
        int cNo = nf * 8 + thr * 2;
        if (r0 < N_NODES)
            *(half2*)(g_h2 + r0 * F2 + cNo) =
                __floats2half2_rn(acc[nf][0] * s0, acc[nf][1] * s0);
        if (r1 < N_NODES)
            *(half2*)(g_h2 + r1 * F2 + cNo) =
                __floats2half2_rn(acc[nf][2] * s1, acc[nf][3] * s1);
    }
}

// ---------------- Gather layer 2: warp per node, 4-way unroll
// Also re-zeroes g_deg[c] for the next call (last consumer of deg).

__global__ void __launch_bounds__(256) k_gather2(float* __restrict__ out,
                                                 const float* __restrict__ b2) {
    int w = (blockIdx.x * blockDim.x + threadIdx.x) >> 5;
    if (w >= N_NODES) return;
    int lane = threadIdx.x & 31;
    int c = w;
    int fo = lane * 2;

    float2 acc = __half22float2(*(const half2*)(g_h2 + c * F2 + fo));
    int start = g_rowptr[c];
    int dg = g_deg[c];
    int end = start + dg;
    if (lane == 0) g_deg[c] = 0;   // reset for next call (only reader is this warp)

    int j = start;
    for (; j + 4 <= end; j += 4) {
        int i0 = g_csr[j], i1 = g_csr[j + 1], i2 = g_csr[j + 2], i3 = g_csr[j + 3];
        float2 v0 = __half22float2(*(const half2*)(g_h2 + i0 * F2 + fo));
        float2 v1 = __half22float2(*(const half2*)(g_h2 + i1 * F2 + fo));
        float2 v2 = __half22float2(*(const half2*)(g_h2 + i2 * F2 + fo));
        float2 v3 = __half22float2(*(const half2*)(g_h2 + i3 * F2 + fo));
        acc.x += (v0.x + v1.x) + (v2.x + v3.x);
        acc.y += (v0.y + v1.y) + (v2.y + v3.y);
    }
    for (; j < end; j++) {
        float2 v0 = __half22float2(*(const half2*)(g_h2 + g_csr[j] * F2 + fo));
        acc.x += v0.x; acc.y += v0.y;
    }

    float s = g_dinv[c];
    float2 bb = *(const float2*)(b2 + fo);
    out[c * F2 + fo + 0] = fmaf(s, acc.x, bb.x);
    out[c * F2 + fo + 1] = fmaf(s, acc.y, bb.y);
}

extern "C" void kernel_launch(void* const* d_in, const int* in_sizes, int n_in,
                              void* d_out, int out_size) {
    const float* x  = (const float*)d_in[0];
    const void*  ei = d_in[1];
    const float* W1 = (const float*)d_in[2];
    const float* b1 = (const float*)d_in[3];
    const float* W2 = (const float*)d_in[4];
    const float* b2 = (const float*)d_in[5];
    float* out = (float*)d_out;

    int E = in_sizes[1] / 2;
    if (E > MAX_E) E = MAX_E;

    // One-time side stream + fork/join events (created outside graph capture).
    static cudaStream_t s_b = 0;
    static cudaEvent_t  e_fork = 0, e_join = 0;
    static int s_ok = -1;
    if (s_ok < 0) {
        s_ok = (cudaStreamCreateWithFlags(&s_b, cudaStreamNonBlocking) == cudaSuccess &&
                cudaEventCreateWithFlags(&e_fork, cudaEventDisableTiming) == cudaSuccess &&
                cudaEventCreateWithFlags(&e_join, cudaEventDisableTiming) == cudaSuccess)
                   ? 1 : 0;
    }

    k_detect<<<1, 256>>>((const long long*)ei);
    k_prep_edges<<<(E + 255) / 256, 256>>>(ei, E);
    k_scan_block<<<NB, 256>>>();   // also writes g_dinv

    if (s_ok) {
        // Fork: CSR finalization runs concurrently with GEMM1.
        cudaEventRecord(e_fork, 0);
        cudaStreamWaitEvent(s_b, e_fork, 0);
        k_scan_top<<<1, 512, 0, s_b>>>();
        k_scan_add<<<(N_NODES + 255) / 256, 256, 0, s_b>>>();
        k_fill<<<(E + 255) / 256, 256, 0, s_b>>>(E);
        cudaEventRecord(e_join, s_b);

        k_gemm1<<<(N_NODES + 127) / 128, 256>>>(x, W1);

        cudaStreamWaitEvent(0, e_join, 0);   // gather1 needs CSR
    } else {
        k_scan_top<<<1, 512>>>();
        k_scan_add<<<(N_NODES + 255) / 256, 256>>>();
        k_fill<<<(E + 255) / 256, 256>>>(E);
        k_gemm1<<<(N_NODES + 127) / 128, 256>>>(x, W1);
    }

    k_gather1<<<(N_NODES * 32 + 255) / 256, 256>>>(b1);
    k_gemm2<<<(N_NODES + 127) / 128, 256>>>(W2);
    k_gather2<<<(N_NODES * 32 + 255) / 256, 256>>>(out, b2);
}